// round 1
// baseline (speedup 1.0000x reference)
#include <cuda_runtime.h>

// OptimizerNetwork: per-row 2-layer LSTM-cell meta-optimizer.
// N=1e6 rows, H=20. Compute-bound in fp32 FMA -> use packed fma.rn.f32x2
// (2x fp32 throughput, PTX-only) with the reduction dim packed in pairs.

typedef unsigned long long ull;

__device__ __forceinline__ ull pk(float a, float b) {
    ull r; asm("mov.b64 %0, {%1,%2};" : "=l"(r) : "f"(a), "f"(b)); return r;
}
__device__ __forceinline__ void upk(ull p, float& a, float& b) {
    asm("mov.b64 {%0,%1}, %2;" : "=f"(a), "=f"(b) : "l"(p));
}
__device__ __forceinline__ ull ffma2(ull a, ull b, ull c) {
    ull r; asm("fma.rn.f32x2 %0, %1, %2, %3;" : "=l"(r) : "l"(a), "l"(b), "l"(c)); return r;
}

__device__ __forceinline__ float sigm(float x) {
    return __fdividef(1.f, 1.f + __expf(-x));
}
__device__ __forceinline__ float tanhx(float x) {
    return __fdividef(2.f, 1.f + __expf(-2.f * x)) - 1.f;
}

struct __align__(16) SW {
    float Wih1[160];   // [80][2]
    float Whh1[1600];  // [80][20]
    float Wih2[1600];  // [80][20]
    float Whh2[1600];  // [80][20]
    float B1[80];      // bih1+bhh1
    float B2[80];      // bih2+bhh2
    float Wout[20];
    float bout;
};

// One LSTM cell for 1 row. Input x given as KPAIR packed f32x2 pairs.
// hin/cin: 10 pairs each. hout kept in registers; cout streamed to gmem.
template <int KPAIR>
__device__ __forceinline__ void lstm_cell(
    const ull* xin, const float* sWih, const float* sWhh, const float* sB,
    const ull* hin, const ull* cin, ull* hout, ull* cout_g)
{
#pragma unroll
    for (int jj = 0; jj < 10; ++jj) {
        float gv[8];
#pragma unroll
        for (int u = 0; u < 2; ++u) {
            const int j = 2 * jj + u;
#pragma unroll
            for (int g = 0; g < 4; ++g) {
                const int r = g * 20 + j;
                ull acc = pk(sB[r], 0.f);
                if (KPAIR == 1) {
                    const ull* wi = (const ull*)(sWih + r * 2);
                    acc = ffma2(xin[0], wi[0], acc);
                } else {
                    const ulonglong2* wi = (const ulonglong2*)(sWih + r * (2 * KPAIR));
#pragma unroll
                    for (int k = 0; k < KPAIR / 2; ++k) {
                        ulonglong2 w = wi[k];
                        acc = ffma2(xin[2 * k],     w.x, acc);
                        acc = ffma2(xin[2 * k + 1], w.y, acc);
                    }
                }
                const ulonglong2* wh = (const ulonglong2*)(sWhh + r * 20);
#pragma unroll
                for (int k = 0; k < 5; ++k) {
                    ulonglong2 w = wh[k];
                    acc = ffma2(hin[2 * k],     w.x, acc);
                    acc = ffma2(hin[2 * k + 1], w.y, acc);
                }
                float lo, hi; upk(acc, lo, hi);
                gv[u * 4 + g] = lo + hi;
            }
        }
        float i0 = sigm(gv[0]), f0 = sigm(gv[1]), g0 = tanhx(gv[2]), o0 = sigm(gv[3]);
        float i1 = sigm(gv[4]), f1 = sigm(gv[5]), g1 = tanhx(gv[6]), o1 = sigm(gv[7]);
        float ca, cb; upk(cin[jj], ca, cb);
        float cn0 = fmaf(f0, ca, i0 * g0);
        float cn1 = fmaf(f1, cb, i1 * g1);
        cout_g[jj] = pk(cn0, cn1);                 // STG.64, frees registers
        hout[jj]   = pk(o0 * tanhx(cn0), o1 * tanhx(cn1));
    }
}

__global__ void __launch_bounds__(128)
optnet_kernel(const float* __restrict__ inp,
              const float* __restrict__ h0, const float* __restrict__ h1,
              const float* __restrict__ c0, const float* __restrict__ c1,
              const float* __restrict__ Wih1, const float* __restrict__ Whh1,
              const float* __restrict__ bih1, const float* __restrict__ bhh1,
              const float* __restrict__ Wih2, const float* __restrict__ Whh2,
              const float* __restrict__ bih2, const float* __restrict__ bhh2,
              const float* __restrict__ Wout, const float* __restrict__ bout,
              float* __restrict__ out, int N)
{
    __shared__ SW sw;
    const int tid = threadIdx.x, bd = blockDim.x;
    for (int i = tid; i < 160;  i += bd) sw.Wih1[i] = Wih1[i];
    for (int i = tid; i < 1600; i += bd) sw.Whh1[i] = Whh1[i];
    for (int i = tid; i < 1600; i += bd) sw.Wih2[i] = Wih2[i];
    for (int i = tid; i < 1600; i += bd) sw.Whh2[i] = Whh2[i];
    for (int i = tid; i < 80;   i += bd) { sw.B1[i] = bih1[i] + bhh1[i];
                                           sw.B2[i] = bih2[i] + bhh2[i]; }
    for (int i = tid; i < 20;   i += bd) sw.Wout[i] = Wout[i];
    if (tid == 0) sw.bout = bout[0];
    __syncthreads();

    const int row = blockIdx.x * bd + tid;
    if (row >= N) return;

    // ---- preprocess (stop_gradient path, elementwise) ----
    float x = inp[row];
    float ax = fabsf(x);
    float pa, pb;
    if (ax >= 4.5399930e-05f) {            // exp(-10)
        pa = __logf(ax + 1e-8f) * 0.1f;
        pb = (x > 0.f) ? 1.f : -1.f;
    } else {
        pa = -1.f;
        pb = 22026.4658f * x;              // exp(10)
    }
    ull xp[1]; xp[0] = pk(pa, pb);

    // ---- output section pointers (tuple order: out, h0n, h1n, c0n, c1n) ----
    float* h0n_out = out + (size_t)N;
    float* h1n_out = out + (size_t)N * 21;
    float* c0n_out = out + (size_t)N * 41;
    float* c1n_out = out + (size_t)N * 61;

    ull hA[10], cA[10], hN[10], hM[10];
    const ulonglong2* p;

    // load h0, c0 (rows are 80B -> 5x LDG.128)
    p = (const ulonglong2*)(h0 + (size_t)row * 20);
#pragma unroll
    for (int q = 0; q < 5; ++q) { ulonglong2 v = p[q]; hA[2*q] = v.x; hA[2*q+1] = v.y; }
    p = (const ulonglong2*)(c0 + (size_t)row * 20);
#pragma unroll
    for (int q = 0; q < 5; ++q) { ulonglong2 v = p[q]; cA[2*q] = v.x; cA[2*q+1] = v.y; }

    // ---- LSTM cell 1 ----
    lstm_cell<1>(xp, sw.Wih1, sw.Whh1, sw.B1, hA, cA, hN,
                 (ull*)(c0n_out + (size_t)row * 20));

    // store h0n
    {
        ulonglong2* q2 = (ulonglong2*)(h0n_out + (size_t)row * 20);
#pragma unroll
        for (int q = 0; q < 5; ++q) { ulonglong2 v; v.x = hN[2*q]; v.y = hN[2*q+1]; q2[q] = v; }
    }

    // load h1, c1
    p = (const ulonglong2*)(h1 + (size_t)row * 20);
#pragma unroll
    for (int q = 0; q < 5; ++q) { ulonglong2 v = p[q]; hA[2*q] = v.x; hA[2*q+1] = v.y; }
    p = (const ulonglong2*)(c1 + (size_t)row * 20);
#pragma unroll
    for (int q = 0; q < 5; ++q) { ulonglong2 v = p[q]; cA[2*q] = v.x; cA[2*q+1] = v.y; }

    // ---- LSTM cell 2 ----
    lstm_cell<10>(hN, sw.Wih2, sw.Whh2, sw.B2, hA, cA, hM,
                  (ull*)(c1n_out + (size_t)row * 20));

    // store h1n
    {
        ulonglong2* q2 = (ulonglong2*)(h1n_out + (size_t)row * 20);
#pragma unroll
        for (int q = 0; q < 5; ++q) { ulonglong2 v; v.x = hM[2*q]; v.y = hM[2*q+1]; q2[q] = v; }
    }

    // ---- output linear ----
    ull acc = pk(sw.bout, 0.f);
    const ulonglong2* wo = (const ulonglong2*)sw.Wout;
#pragma unroll
    for (int k = 0; k < 5; ++k) {
        ulonglong2 w = wo[k];
        acc = ffma2(hM[2*k],     w.x, acc);
        acc = ffma2(hM[2*k + 1], w.y, acc);
    }
    float lo, hi; upk(acc, lo, hi);
    out[row] = lo + hi;
}

extern "C" void kernel_launch(void* const* d_in, const int* in_sizes, int n_in,
                              void* d_out, int out_size)
{
    const float* inp  = (const float*)d_in[0];
    const float* h0   = (const float*)d_in[1];
    const float* h1   = (const float*)d_in[2];
    const float* c0   = (const float*)d_in[3];
    const float* c1   = (const float*)d_in[4];
    const float* Wih1 = (const float*)d_in[5];
    const float* Whh1 = (const float*)d_in[6];
    const float* bih1 = (const float*)d_in[7];
    const float* bhh1 = (const float*)d_in[8];
    const float* Wih2 = (const float*)d_in[9];
    const float* Whh2 = (const float*)d_in[10];
    const float* bih2 = (const float*)d_in[11];
    const float* bhh2 = (const float*)d_in[12];
    const float* Wout = (const float*)d_in[13];
    const float* bout = (const float*)d_in[14];

    const int N = in_sizes[0];
    const int bd = 128;
    const int blocks = (N + bd - 1) / bd;
    optnet_kernel<<<blocks, bd>>>(inp, h0, h1, c0, c1,
                                  Wih1, Whh1, bih1, bhh1,
                                  Wih2, Whh2, bih2, bhh2,
                                  Wout, bout, (float*)d_out, N);
}